// round 4
// baseline (speedup 1.0000x reference)
#include <cuda_runtime.h>
#include <cuda_bf16.h>
#include <cstdint>

// Embedding gather: out[b, t, :] = weight[idxes[b, t], :]
// idxes: [8, 2048] int32, weight: [50257, 1024] f32, out: [8,2048,1024] f32
//
// R4: cp.async (LDGSTS) gather. Register-resident MLP batching was defeated
// by ptxas twice (regs pinned at 32 -> loads interleaved with stores).
// LDGSTS has no destination register, so ptxas cannot collapse the batch:
// each thread issues 8 fire-and-forget 16B gather loads into smem, waits,
// then drains its own slots (no cross-thread sharing -> no __syncthreads).

#define FEATURES 1024
#define VEC4_PER_ROW (FEATURES / 4)   // 256
#define ROWS_PER_CTA 8

__global__ __launch_bounds__(256) void embedding_gather_cpasync_kernel(
    const int* __restrict__ idxes,
    const float4* __restrict__ weight,
    float4* __restrict__ out,
    int n_rows)
{
    __shared__ float4 buf[ROWS_PER_CTA][VEC4_PER_ROW];   // 32 KB

    const int t = threadIdx.x;                 // 0..255 = column slot
    const int base = blockIdx.x * ROWS_PER_CTA;

    if (base + ROWS_PER_CTA <= n_rows) {
        int idx[ROWS_PER_CTA];
#pragma unroll
        for (int r = 0; r < ROWS_PER_CTA; r++)
            idx[r] = idxes[base + r];          // broadcast loads

        // First half: 4 async gather loads, commit as group 0.
#pragma unroll
        for (int r = 0; r < 4; r++) {
            const float4* src = weight + (size_t)idx[r] * VEC4_PER_ROW + t;
            uint32_t dst = (uint32_t)__cvta_generic_to_shared(&buf[r][t]);
            asm volatile("cp.async.cg.shared.global [%0], [%1], 16;"
                         :: "r"(dst), "l"(src));
        }
        asm volatile("cp.async.commit_group;" ::: "memory");

        // Second half: group 1.
#pragma unroll
        for (int r = 4; r < ROWS_PER_CTA; r++) {
            const float4* src = weight + (size_t)idx[r] * VEC4_PER_ROW + t;
            uint32_t dst = (uint32_t)__cvta_generic_to_shared(&buf[r][t]);
            asm volatile("cp.async.cg.shared.global [%0], [%1], 16;"
                         :: "r"(dst), "l"(src));
        }
        asm volatile("cp.async.commit_group;" ::: "memory");

        // Drain first half while second half is still in flight.
        asm volatile("cp.async.wait_group 1;" ::: "memory");
#pragma unroll
        for (int r = 0; r < 4; r++)
            out[(size_t)(base + r) * VEC4_PER_ROW + t] = buf[r][t];

        asm volatile("cp.async.wait_group 0;" ::: "memory");
#pragma unroll
        for (int r = 4; r < ROWS_PER_CTA; r++)
            out[(size_t)(base + r) * VEC4_PER_ROW + t] = buf[r][t];
    } else {
        // Tail (unused at 16384 rows; kept for safety).
        for (int r = 0; r < ROWS_PER_CTA; r++) {
            int row = base + r;
            if (row >= n_rows) break;
            int src = idxes[row];
            out[(size_t)row * VEC4_PER_ROW + t] =
                __ldg(weight + (size_t)src * VEC4_PER_ROW + t);
        }
    }
}

extern "C" void kernel_launch(void* const* d_in, const int* in_sizes, int n_in,
                              void* d_out, int out_size)
{
    const int*    idxes  = (const int*)d_in[0];
    const float4* weight = (const float4*)d_in[1];
    float4*       out    = (float4*)d_out;

    int n_rows = in_sizes[0];      // 8 * 2048 = 16384
    int n_ctas = (n_rows + ROWS_PER_CTA - 1) / ROWS_PER_CTA;

    embedding_gather_cpasync_kernel<<<n_ctas, 256>>>(idxes, weight, out, n_rows);
}